// round 1
// baseline (speedup 1.0000x reference)
#include <cuda_runtime.h>
#include <math.h>

#define BATCH   64
#define IN_F    512
#define OUT_F   512
#define NDIM    8
#define NBLK    64      // OB = IB = 64

// Scratch (no allocations allowed -> __device__ globals)
__device__ float gW[OUT_F * IN_F];              // scaled, masked w   (1 MB)
__device__ float gA[NDIM * NBLK * NBLK];        // gA[d][i][o] = exp(g[d,o,i])  (128 KB)
__device__ float gPart[8 * BATCH * OUT_F];      // out-GEMM k-split partials (1 MB)

// ---------------------------------------------------------------------------
// K1: per-row weight prep. One block (128 thr) per row r of W.
//   w_unnorm = exp(W) on diag block, W on lower blocks, 0 above
//   wsn = sum(w_unnorm^2);  w = exp(diag_w)*w_unnorm*rsqrt(wsn)
//   gA[d][i][o] = exp(diag_w[r] - 0.5*log(wsn) + W[r, d*64+i]),  r = d*64+o
// ---------------------------------------------------------------------------
__global__ void k_weights(const float* __restrict__ W,
                          const float* __restrict__ diag_w) {
    const int r   = blockIdx.x;
    const int rb  = r >> 6;                // block-row index (0..7)
    const int lo  = rb << 6;               // diag block col start
    const int hi  = lo + 64;               // diag block col end
    const int tid = threadIdx.x;

    const float* Wrow = W + r * IN_F;
    float wv[4], wu[4];
    float ss = 0.f;
    #pragma unroll
    for (int j = 0; j < 4; j++) {
        const int c = tid + j * 128;
        const float wval = Wrow[c];
        wv[j] = wval;
        float u;
        if (c >= hi)      u = 0.f;
        else if (c >= lo) u = __expf(wval);
        else              u = wval;
        wu[j] = u;
        ss += u * u;
    }
    // block reduce (128 threads = 4 warps)
    #pragma unroll
    for (int off = 16; off > 0; off >>= 1)
        ss += __shfl_down_sync(0xffffffffu, ss, off);
    __shared__ float sred[4];
    __shared__ float sbc[2];
    if ((tid & 31) == 0) sred[tid >> 5] = ss;
    __syncthreads();
    if (tid == 0) {
        const float wsn = sred[0] + sred[1] + sred[2] + sred[3];
        const float dv  = diag_w[r];
        sbc[0] = __expf(dv) * rsqrtf(wsn);       // row scale for w
        sbc[1] = dv - 0.5f * __logf(wsn);        // c1 for g
    }
    __syncthreads();
    const float scale = sbc[0];
    const float c1    = sbc[1];
    const int   o     = r - lo;
    #pragma unroll
    for (int j = 0; j < 4; j++) {
        const int c = tid + j * 128;
        gW[r * IN_F + c] = scale * wu[j];
        if (c >= lo && c < hi) {
            const int i = c - lo;
            gA[(rb * 64 + i) * 64 + o] = __expf(c1 + wv[j]);   // [d][i][o]
        }
    }
}

// ---------------------------------------------------------------------------
// K2a: out partial GEMM.  grid (8 r-tiles, 8 k-chunks), 256 thr.
//   part[kc][b][r] = sum_{k in chunk} inputs[b,k] * gW[r,k]
// ---------------------------------------------------------------------------
__global__ void k_out_partial(const float* __restrict__ inp) {
    __shared__ float sIn[64][65];   // [b][k], pad -> conflict-free strided reads
    __shared__ float sW [64][65];   // [r][k]
    const int rt = blockIdx.x;
    const int kc = blockIdx.y;
    const int tid = threadIdx.x;

    for (int idx = tid; idx < 4096; idx += 256) {
        const int row = idx >> 6, col = idx & 63;
        sIn[row][col] = inp[row * IN_F + kc * 64 + col];
        sW [row][col] = gW[(rt * 64 + row) * IN_F + kc * 64 + col];
    }
    __syncthreads();

    const int b_t = tid & 15;   // 16 x4 -> 64 b
    const int r_t = tid >> 4;   // 16 x4 -> 64 r
    float acc[4][4] = {};
    #pragma unroll 8
    for (int kk = 0; kk < 64; kk++) {
        float a[4], w[4];
        #pragma unroll
        for (int j = 0; j < 4; j++) a[j] = sIn[b_t * 4 + j][kk];
        #pragma unroll
        for (int j = 0; j < 4; j++) w[j] = sW[r_t * 4 + j][kk];
        #pragma unroll
        for (int i = 0; i < 4; i++)
            #pragma unroll
            for (int j = 0; j < 4; j++)
                acc[i][j] += a[i] * w[j];
    }
    float* part = gPart + kc * (BATCH * OUT_F);
    #pragma unroll
    for (int i = 0; i < 4; i++) {
        const int b = b_t * 4 + i;
        float4 v = make_float4(acc[i][0], acc[i][1], acc[i][2], acc[i][3]);
        *(float4*)(part + b * OUT_F + rt * 64 + r_t * 4) = v;
    }
}

// ---------------------------------------------------------------------------
// K2b: reduce the 8 k-chunk partials + bias -> out  (first 32768 floats)
// ---------------------------------------------------------------------------
__global__ void k_out_reduce(const float* __restrict__ bias,
                             float* __restrict__ outp) {
    const int idx = blockIdx.x * 256 + threadIdx.x;    // < 32768
    const int r = idx & 511;
    float s = bias[r];
    #pragma unroll
    for (int kc = 0; kc < 8; kc++) s += gPart[kc * (BATCH * OUT_F) + idx];
    outp[idx] = s;
}

// ---------------------------------------------------------------------------
// K3: jac. One CTA per (b,d) pair: bid = b*8 + d.  256 thr, 4x4 reg tile.
//   C[o][k] = sum_i gA[d][i][o] * exp(grad[b,d,i,k]);  jac = log(C)
//   grad block is contiguous at grad + bid*4096, laid out [i][k] -> direct
//   coalesced copy+exp into Bs (no transpose needed).
// ---------------------------------------------------------------------------
__global__ void k_jac(const float* __restrict__ grad,
                      float* __restrict__ outp) {
    __shared__ float As[4096];   // [i][o]
    __shared__ float Bs[4096];   // [i][k]
    const int bid = blockIdx.x;
    const int d   = bid & 7;
    const int tid = threadIdx.x;

    const float4* a4 = (const float4*)(gA + d * 4096);
    const float4* g4 = (const float4*)(grad + bid * 4096);
    float4* As4 = (float4*)As;
    float4* Bs4 = (float4*)Bs;
    #pragma unroll
    for (int idx = tid; idx < 1024; idx += 256) {
        As4[idx] = a4[idx];
        const float4 v = g4[idx];
        Bs4[idx] = make_float4(__expf(v.x), __expf(v.y), __expf(v.z), __expf(v.w));
    }
    __syncthreads();

    const int k_t = tid & 15;    // 16 x4 -> 64 k
    const int o_t = tid >> 4;    // 16 x4 -> 64 o
    float acc[4][4] = {};
    const float* ap = As + o_t * 4;
    const float* bp = Bs + k_t * 4;
    #pragma unroll 8
    for (int ii = 0; ii < 64; ii++) {
        const float4 a  = *(const float4*)(ap + ii * 64);
        const float4 bv = *(const float4*)(bp + ii * 64);
        acc[0][0] += a.x * bv.x; acc[0][1] += a.x * bv.y; acc[0][2] += a.x * bv.z; acc[0][3] += a.x * bv.w;
        acc[1][0] += a.y * bv.x; acc[1][1] += a.y * bv.y; acc[1][2] += a.y * bv.z; acc[1][3] += a.y * bv.w;
        acc[2][0] += a.z * bv.x; acc[2][1] += a.z * bv.y; acc[2][2] += a.z * bv.z; acc[2][3] += a.z * bv.w;
        acc[3][0] += a.w * bv.x; acc[3][1] += a.w * bv.y; acc[3][2] += a.w * bv.z; acc[3][3] += a.w * bv.w;
    }

    float* jb = outp + 32768 + bid * 4096;   // jac block [o][k]
    #pragma unroll
    for (int jo = 0; jo < 4; jo++) {
        const int o = o_t * 4 + jo;
        float4 v = make_float4(__logf(acc[jo][0]), __logf(acc[jo][1]),
                               __logf(acc[jo][2]), __logf(acc[jo][3]));
        *(float4*)(jb + o * 64 + k_t * 4) = v;
    }
}

// ---------------------------------------------------------------------------
// inputs: [0] inputs (64x512 f32), [1] grad (64x8x64x64 f32),
//         [2] W (512x512 f32), [3] diag_w (512 f32), [4] bias (512 f32)
// d_out:  out (64x512) followed by jac (64x8x64x64), f32
// ---------------------------------------------------------------------------
extern "C" void kernel_launch(void* const* d_in, const int* in_sizes, int n_in,
                              void* d_out, int out_size) {
    const float* inputs = (const float*)d_in[0];
    const float* grad   = (const float*)d_in[1];
    const float* W      = (const float*)d_in[2];
    const float* diag_w = (const float*)d_in[3];
    const float* bias   = (const float*)d_in[4];
    float* outp = (float*)d_out;

    k_weights<<<512, 128>>>(W, diag_w);
    k_out_partial<<<dim3(8, 8), 256>>>(inputs);
    k_out_reduce<<<128, 256>>>(bias, outp);
    k_jac<<<512, 256>>>(grad, outp);
}